// round 11
// baseline (speedup 1.0000x reference)
#include <cuda_runtime.h>
#include <cuda_bf16.h>

// ===========================================================================
// EuclideanCodebook: ind = argmax_c ( x·e_c - 0.5||e_c||^2 ), q = embed[ind].
// R11: 2-term bf16 split GEMM (x = xh+xl, e ~= eh; x·e ~= xh·eh + xl·eh).
// Epilogue tracks TOP-4 approx scores per row. Candidate-set rescue:
//   gap12 >= T            -> argmax certain (T = 0.028*||x||, ~8.8 sigma)
//   gap14 >= T > gap12    -> true argmax in {i1,i2,i3}: re-score 3 codes
//   else (rare)           -> full exact rescan
// ===========================================================================

#define NROWS   131072
#define KCODES  1024
#define STRIDE_A 528            // A row: 512B payload [xh|xl] + 16B pad
#define STRIDE_B 272            // B row: 256B payload [eh] + 16B pad

// smem byte offsets (main kernel)
#define S_HN    0                         // 1024 floats
#define S_XN    4096                      // 128 floats (row ||x||^2)
#define S_A     4608                      // 128 x 528
#define S_B0    (S_A  + 67584)            // 128 x 272
#define S_B1    (S_B0 + 34816)
#define S_V0    (S_B1 + 34816)            // float[4][128] x4 value ranks
#define S_V1    (S_V0 + 2048)
#define S_V2    (S_V1 + 2048)
#define S_V3    (S_V2 + 2048)
#define S_I0    (S_V3 + 2048)             // int[4][128] x3 index ranks
#define S_I1    (S_I0 + 2048)
#define S_I2    (S_I1 + 2048)
#define S_IND   (S_I2 + 2048)             // int[128]
#define S_TOTAL (S_IND + 512)             // 156672 B

// __device__ scratch (allocation-free)
__device__ __align__(16) __nv_bfloat16 g_Eh[KCODES * 128];
__device__ float g_hn[KCODES];
__device__ int   g_tcnt;                  // triple-rescue count
__device__ int4  g_trows[NROWS];          // {row, i0, i1, i2}
__device__ int   g_fcnt;                  // full-rescue count
__device__ int   g_frows[NROWS];

// ---------------------------------------------------------------------------
__device__ __forceinline__ unsigned smem_u32(const void* p) {
    unsigned a;
    asm("{ .reg .u64 t; cvta.to.shared.u64 t, %1; cvt.u32.u64 %0, t; }"
        : "=r"(a) : "l"(p));
    return a;
}

#define LDSM_X4(r, addr)                                                      \
    asm volatile("ldmatrix.sync.aligned.m8n8.x4.shared.b16 {%0,%1,%2,%3}, [%4];" \
        : "=r"((r)[0]), "=r"((r)[1]), "=r"((r)[2]), "=r"((r)[3]) : "r"(addr))

#define MMA16816(d, a, b0, b1)                                                \
    asm volatile("mma.sync.aligned.m16n8k16.row.col.f32.bf16.bf16.f32 "       \
        "{%0,%1,%2,%3}, {%4,%5,%6,%7}, {%8,%9}, {%0,%1,%2,%3};"               \
        : "+f"((d)[0]), "+f"((d)[1]), "+f"((d)[2]), "+f"((d)[3])              \
        : "r"((a)[0]), "r"((a)[1]), "r"((a)[2]), "r"((a)[3]), "r"(b0), "r"(b1))

#define CP_COMMIT() asm volatile("cp.async.commit_group;" ::: "memory")
#define CP_WAIT1()  asm volatile("cp.async.wait_group 1;" ::: "memory")

__device__ __forceinline__ unsigned pack_bf16x2(float a, float b) {
    __nv_bfloat162 h = __floats2bfloat162_rn(a, b);
    return *(unsigned*)&h;
}

// top-4 insert: V0>=V1>=V2>=V3 with indices for top-3, ties -> lower index
struct Top4 { float V0, V1, V2, V3; int I0, I1, I2; };
__device__ __forceinline__ void t4_init(Top4& t) {
    t.V0 = t.V1 = t.V2 = t.V3 = -3.4e38f;
    t.I0 = t.I1 = t.I2 = 0x7fffffff;
}
__device__ __forceinline__ void t4_ins(Top4& t, float v, int i) {
    if (v > t.V0 || (v == t.V0 && i < t.I0)) {
        t.V3 = t.V2; t.V2 = t.V1; t.I2 = t.I1; t.V1 = t.V0; t.I1 = t.I0;
        t.V0 = v; t.I0 = i;
    } else if (v > t.V1 || (v == t.V1 && i < t.I1)) {
        t.V3 = t.V2; t.V2 = t.V1; t.I2 = t.I1; t.V1 = v; t.I1 = i;
    } else if (v > t.V2 || (v == t.V2 && i < t.I2)) {
        t.V3 = t.V2; t.V2 = v; t.I2 = i;
    } else if (v > t.V3) {
        t.V3 = v;
    }
}

// ---------------------------------------------------------------------------
// prep_e: warp per code. bf16 convert + 0.5||e||^2 + counter reset.
// ---------------------------------------------------------------------------
__global__ void prep_e(const float* __restrict__ embed) {
    int w = (blockIdx.x * blockDim.x + threadIdx.x) >> 5;   // code
    int lane = threadIdx.x & 31;
    if (w == 0 && lane == 0) { g_tcnt = 0; g_fcnt = 0; }
    if (w >= KCODES) return;
    float4 v = ((const float4*)(embed + (size_t)w * 128))[lane];
    float s = v.x * v.x + v.y * v.y + v.z * v.z + v.w * v.w;
#pragma unroll
    for (int off = 16; off > 0; off >>= 1)
        s += __shfl_xor_sync(0xffffffffu, s, off);
    if (lane == 0) g_hn[w] = 0.5f * s;
    uint2 o;
    o.x = pack_bf16x2(v.x, v.y);
    o.y = pack_bf16x2(v.z, v.w);
    ((uint2*)(g_Eh + (size_t)w * 128))[lane] = o;
}

// ---------------------------------------------------------------------------
__device__ __forceinline__ void load_B_async(unsigned sb, int ch, int bufOff, int tid) {
    const char* src = (const char*)(g_Eh + (size_t)ch * 128 * 128);
#pragma unroll
    for (int it = 0; it < 8; it++) {
        int idx = tid + it * 256;
        int r = idx >> 4, kk = idx & 15;
        unsigned dst = sb + bufOff + r * STRIDE_B + kk * 16;
        asm volatile("cp.async.cg.shared.global [%0], [%1], 16;"
                     :: "r"(dst), "l"(src + r * 256 + kk * 16));
    }
}

// ---------------------------------------------------------------------------
// main: 1024 CTAs x 256 threads; CTA = 128 rows x 1024 codes (8 chunks x 128).
// ---------------------------------------------------------------------------
__global__ __launch_bounds__(256, 1)
void vq_main(const float* __restrict__ x, const float* __restrict__ embed,
             float* __restrict__ out_ind, float* __restrict__ out_q) {
    extern __shared__ char smem[];
    unsigned sb = smem_u32(smem);
    const int tid  = threadIdx.x;
    const int lane = tid & 31, wid = tid >> 5;
    const int wr = wid & 1, wc = wid >> 1;
    const int rowBase = blockIdx.x * 128;
    float* hnS = (float*)(smem + S_HN);
    float* xnS = (float*)(smem + S_XN);

    // ---- prologue: hn + fused x->bf16-split A tile (+ row norms) ----
    ((float4*)hnS)[tid] = ((const float4*)g_hn)[tid];
    {
        const float4* src = (const float4*)(x + (size_t)rowBase * 128);
#pragma unroll
        for (int it = 0; it < 16; it++) {
            int idx = tid + it * 256;
            int r = idx >> 5, kk = idx & 31;    // one warp covers one row
            float4 v = src[idx];
            float loc = v.x * v.x + v.y * v.y + v.z * v.z + v.w * v.w;
            __nv_bfloat16 h0 = __float2bfloat16(v.x), h1 = __float2bfloat16(v.y);
            __nv_bfloat16 h2 = __float2bfloat16(v.z), h3 = __float2bfloat16(v.w);
            uint2 hi, lo;
            { __nv_bfloat162 t0(h0, h1), t1(h2, h3);
              hi.x = *(unsigned*)&t0; hi.y = *(unsigned*)&t1; }
            lo.x = pack_bf16x2(v.x - __bfloat162float(h0), v.y - __bfloat162float(h1));
            lo.y = pack_bf16x2(v.z - __bfloat162float(h2), v.w - __bfloat162float(h3));
            *(uint2*)(smem + S_A + r * STRIDE_A + kk * 8)       = hi;
            *(uint2*)(smem + S_A + r * STRIDE_A + 256 + kk * 8) = lo;
#pragma unroll
            for (int off = 16; off > 0; off >>= 1)
                loc += __shfl_xor_sync(0xffffffffu, loc, off);
            if (kk == 0) xnS[r] = loc;
        }
    }
    load_B_async(sb, 0, S_B0, tid); CP_COMMIT();
    load_B_async(sb, 1, S_B1, tid); CP_COMMIT();

    Top4 t4[8];
#pragma unroll
    for (int s = 0; s < 8; s++) t4_init(t4[s]);

    const unsigned aRowOff = (unsigned)(wr * 64 + (lane & 15)) * STRIDE_A
                             + ((lane >> 4) * 16);
    const unsigned bRowOff = (unsigned)(wc * 32 + ((lane >> 4) * 8) + (lane & 7)) * STRIDE_B
                             + (((lane >> 3) & 1) * 16);

    for (int ch = 0; ch < 8; ch++) {
        CP_WAIT1();
        __syncthreads();                       // chunk ch resident

        float d[4][4][4];
#pragma unroll
        for (int mt = 0; mt < 4; mt++)
#pragma unroll
            for (int nt = 0; nt < 4; nt++)
#pragma unroll
                for (int e = 0; e < 4; e++) d[mt][nt][e] = 0.f;

        const unsigned Abase = sb + S_A + aRowOff;
        const unsigned Bbase = sb + ((ch & 1) ? S_B1 : S_B0) + bRowOff;

#pragma unroll
        for (int kk = 0; kk < 8; kk++) {
            unsigned ah[4][4], al[4][4];
#pragma unroll
            for (int mt = 0; mt < 4; mt++) {
                LDSM_X4(ah[mt], Abase + mt * (16 * STRIDE_A) + kk * 32);
                LDSM_X4(al[mt], Abase + mt * (16 * STRIDE_A) + 256 + kk * 32);
            }
            unsigned bh[2][4];
#pragma unroll
            for (int j = 0; j < 2; j++)
                LDSM_X4(bh[j], Bbase + j * (16 * STRIDE_B) + kk * 32);
#pragma unroll
            for (int mt = 0; mt < 4; mt++)
#pragma unroll
                for (int nt = 0; nt < 4; nt++) {
                    unsigned b0 = bh[nt >> 1][(nt & 1) * 2];
                    unsigned b1 = bh[nt >> 1][(nt & 1) * 2 + 1];
                    MMA16816(d[mt][nt], ah[mt], b0, b1);   // xh·eh
                    MMA16816(d[mt][nt], al[mt], b0, b1);   // xl·eh
                }
        }

        // ---- fold -0.5||e||^2, update per-row-slot top-4 ----
        const int cb = ch * 128 + wc * 32 + (lane & 3) * 2;
#pragma unroll
        for (int mt = 0; mt < 4; mt++)
#pragma unroll
            for (int h = 0; h < 2; h++) {
                const int s = mt * 2 + h;
#pragma unroll
                for (int nt = 0; nt < 4; nt++)
#pragma unroll
                    for (int e = 0; e < 2; e++) {
                        int code = cb + nt * 8 + e;
                        float v = d[mt][nt][h * 2 + e] - hnS[code];
                        t4_ins(t4[s], v, code);
                    }
            }

        __syncthreads();
        if (ch + 2 < 8) { load_B_async(sb, ch + 2, (ch & 1) ? S_B1 : S_B0, tid); CP_COMMIT(); }
    }

    // ---- merge top-4 across 4 lanes sharing each row (xor 1, 2) ----
#pragma unroll
    for (int s = 0; s < 8; s++) {
#pragma unroll
        for (int off = 1; off <= 2; off <<= 1) {
            float oV0 = __shfl_xor_sync(0xffffffffu, t4[s].V0, off);
            float oV1 = __shfl_xor_sync(0xffffffffu, t4[s].V1, off);
            float oV2 = __shfl_xor_sync(0xffffffffu, t4[s].V2, off);
            float oV3 = __shfl_xor_sync(0xffffffffu, t4[s].V3, off);
            int   oI0 = __shfl_xor_sync(0xffffffffu, t4[s].I0, off);
            int   oI1 = __shfl_xor_sync(0xffffffffu, t4[s].I1, off);
            int   oI2 = __shfl_xor_sync(0xffffffffu, t4[s].I2, off);
            t4_ins(t4[s], oV0, oI0);
            t4_ins(t4[s], oV1, oI1);
            t4_ins(t4[s], oV2, oI2);
            t4_ins(t4[s], oV3, 0x7fffffff);
        }
    }
    if ((lane & 3) == 0) {
#pragma unroll
        for (int s = 0; s < 8; s++) {
            int mt = s >> 1, h = s & 1;
            int r = wr * 64 + mt * 16 + h * 8 + (lane >> 2);
            int o = wc * 128 + r;
            ((float*)(smem + S_V0))[o] = t4[s].V0;
            ((float*)(smem + S_V1))[o] = t4[s].V1;
            ((float*)(smem + S_V2))[o] = t4[s].V2;
            ((float*)(smem + S_V3))[o] = t4[s].V3;
            ((int*)(smem + S_I0))[o]   = t4[s].I0;
            ((int*)(smem + S_I1))[o]   = t4[s].I1;
            ((int*)(smem + S_I2))[o]   = t4[s].I2;
        }
    }
    __syncthreads();

    // ---- merge 4 strips, write ind, classify rescue tiers ----
    if (tid < 128) {
        Top4 t; t4_init(t);
#pragma unroll
        for (int w = 0; w < 4; w++) {
            int o = w * 128 + tid;
            t4_ins(t, ((const float*)(smem + S_V0))[o], ((const int*)(smem + S_I0))[o]);
            t4_ins(t, ((const float*)(smem + S_V1))[o], ((const int*)(smem + S_I1))[o]);
            t4_ins(t, ((const float*)(smem + S_V2))[o], ((const int*)(smem + S_I2))[o]);
            t4_ins(t, ((const float*)(smem + S_V3))[o], 0x7fffffff);
        }
        int row = rowBase + tid;
        if (out_ind) out_ind[row] = (float)t.I0;
        float T = 0.028f * sqrtf(xnS[tid]);
        if (t.V0 - t.V1 < T) {
            if (t.V0 - t.V3 >= T) {
                int s = atomicAdd(&g_tcnt, 1);
                if (s < NROWS) g_trows[s] = make_int4(row, t.I0, t.I1, t.I2);
            } else {
                int s = atomicAdd(&g_fcnt, 1);
                if (s < NROWS) g_frows[s] = row;
            }
        }
        ((int*)(smem + S_IND))[tid] = t.I0;
    }
    __syncthreads();

    // ---- cooperative gather of quantize rows ----
    if (out_q) {
        const int* inds = (const int*)(smem + S_IND);
        for (int i = tid; i < 128 * 32; i += 256) {
            int r = i >> 5, c4 = i & 31;
            float4 v = ((const float4*)(embed + (size_t)inds[r] * 128))[c4];
            ((float4*)(out_q + (size_t)(rowBase + r) * 128))[c4] = v;
        }
    }
}

// ---------------------------------------------------------------------------
// triple rescue: warp per flagged row; exactly re-score 3 candidate codes.
// ---------------------------------------------------------------------------
__global__ __launch_bounds__(256, 8)
void triple_rescue(const float* __restrict__ x,
                   const float* __restrict__ embed,
                   float* __restrict__ out_ind,
                   float* __restrict__ out_q) {
    const int lane = threadIdx.x & 31;
    const int gw = (blockIdx.x * blockDim.x + threadIdx.x) >> 5;
    const int nw = (gridDim.x * blockDim.x) >> 5;
    const int cnt = g_tcnt < NROWS ? g_tcnt : NROWS;

    for (int it = gw; it < cnt; it += nw) {
        int4 job = g_trows[it];
        float4 xv = ((const float4*)(x + (size_t)job.x * 128))[lane];
        float s[3];
        int   idx[3] = {job.y, job.z, job.w};
#pragma unroll
        for (int c = 0; c < 3; c++) {
            float4 ev = ((const float4*)(embed + (size_t)idx[c] * 128))[lane];
            float p = fmaf(xv.x, ev.x, fmaf(xv.y, ev.y,
                      fmaf(xv.z, ev.z, xv.w * ev.w)));
#pragma unroll
            for (int off = 16; off > 0; off >>= 1)
                p += __shfl_xor_sync(0xffffffffu, p, off);
            s[c] = p - g_hn[idx[c]];
        }
        // pick winner: value desc, index asc
        float B = s[0]; int I = idx[0];
        if (s[1] > B || (s[1] == B && idx[1] < I)) { B = s[1]; I = idx[1]; }
        if (s[2] > B || (s[2] == B && idx[2] < I)) { B = s[2]; I = idx[2]; }
        if (lane == 0 && out_ind) out_ind[job.x] = (float)I;
        if (out_q)
            ((float4*)(out_q + (size_t)job.x * 128))[lane] =
                ((const float4*)(embed + (size_t)I * 128))[lane];
    }
}

// ---------------------------------------------------------------------------
// full rescue: block per rare row; exact fp32 scan over all codes.
// ---------------------------------------------------------------------------
__global__ __launch_bounds__(256, 4)
void full_rescue(const float* __restrict__ x,
                 const float* __restrict__ embed,
                 float* __restrict__ out_ind,
                 float* __restrict__ out_q) {
    __shared__ float4 xs4[32];
    __shared__ float bvs[256];
    __shared__ int   bis[256];
    const int tid = threadIdx.x;
    const int cnt = g_fcnt < NROWS ? g_fcnt : NROWS;

    for (int it = blockIdx.x; it < cnt; it += gridDim.x) {
        int row = g_frows[it];
        if (tid < 32) xs4[tid] = ((const float4*)(x + (size_t)row * 128))[tid];
        __syncthreads();

        float bv = -3.4e38f;
        int   bi = 0;
#pragma unroll
        for (int j = 0; j < 4; j++) {
            int c = j * 256 + tid;
            const float4* e4 = (const float4*)(embed + (size_t)c * 128);
            float s0 = 0.f, s1 = 0.f, s2 = 0.f, s3 = 0.f;
#pragma unroll
            for (int i = 0; i < 8; i++) {
                float4 xa = xs4[i * 4 + 0], ea = e4[i * 4 + 0];
                float4 xb = xs4[i * 4 + 1], eb = e4[i * 4 + 1];
                float4 xc = xs4[i * 4 + 2], ec = e4[i * 4 + 2];
                float4 xd = xs4[i * 4 + 3], ed = e4[i * 4 + 3];
                s0 = fmaf(xa.x, ea.x, fmaf(xa.y, ea.y, fmaf(xa.z, ea.z, fmaf(xa.w, ea.w, s0))));
                s1 = fmaf(xb.x, eb.x, fmaf(xb.y, eb.y, fmaf(xb.z, eb.z, fmaf(xb.w, eb.w, s1))));
                s2 = fmaf(xc.x, ec.x, fmaf(xc.y, ec.y, fmaf(xc.z, ec.z, fmaf(xc.w, ec.w, s2))));
                s3 = fmaf(xd.x, ed.x, fmaf(xd.y, ed.y, fmaf(xd.z, ed.z, fmaf(xd.w, ed.w, s3))));
            }
            float s = (s0 + s1) + (s2 + s3) - g_hn[c];
            if (s > bv) { bv = s; bi = c; }
        }
        bvs[tid] = bv; bis[tid] = bi;
        __syncthreads();
#pragma unroll
        for (int st = 128; st > 0; st >>= 1) {
            if (tid < st) {
                float ov = bvs[tid + st]; int oi = bis[tid + st];
                if (ov > bvs[tid] || (ov == bvs[tid] && oi < bis[tid])) {
                    bvs[tid] = ov; bis[tid] = oi;
                }
            }
            __syncthreads();
        }
        int fi = bis[0];
        if (tid == 0 && out_ind) out_ind[row] = (float)fi;
        if (out_q && tid < 32)
            ((float4*)(out_q + (size_t)row * 128))[tid] =
                ((const float4*)(embed + (size_t)fi * 128))[tid];
        __syncthreads();
    }
}

// ---------------------------------------------------------------------------
extern "C" void kernel_launch(void* const* d_in, const int* in_sizes, int n_in,
                              void* d_out, int out_size) {
    const float* x     = (const float*)d_in[0];
    const float* embed = (const float*)d_in[1];
    const int N = in_sizes[0] / 128;   // 131072

    float* out     = (float*)d_out;
    float* out_ind = out;              // layout: [ind (N)][quantize (N*128)]
    float* out_q   = out + N;
    long long os = (long long)out_size;
    if (os == (long long)N * 128) { out_ind = nullptr; out_q = out; }
    else if (os == (long long)N)  { out_q = nullptr; }

    prep_e<<<KCODES / 8, 256>>>(embed);

    cudaFuncSetAttribute(vq_main, cudaFuncAttributeMaxDynamicSharedMemorySize,
                         S_TOTAL);
    vq_main<<<N / 128, 256, S_TOTAL>>>(x, embed, out_ind, out_q);

    triple_rescue<<<512, 256>>>(x, embed, out_ind, out_q);
    full_rescue<<<256, 256>>>(x, embed, out_ind, out_q);
}

// round 12
// speedup vs baseline: 1.6804x; 1.6804x over previous
#include <cuda_runtime.h>
#include <cuda_bf16.h>

// ===========================================================================
// EuclideanCodebook: ind = argmax_c ( x·e_c - 0.5||e_c||^2 ), q = embed[ind].
// R12: 2-term bf16 split GEMM (x = xh+xl, e ~= eh), 64-row CTA -> 113KB smem
// -> 2 CTAs/SM (latency hiding), regs < 128 (no spills).
// Epilogue: top-3 values + top-2 indices per row. Tiers (T = 0.028*||x||):
//   gap12 >= T -> done ; gap13 >= T -> re-score {i1,i2} ; else batched full.
// ===========================================================================

#define NROWS   131072
#define KCODES  1024
#define BM      64
#define STRIDE_A 528            // A row: 512B payload [xh|xl] + 16B pad
#define STRIDE_B 272            // B row: 256B payload [eh] + 16B pad

// smem byte offsets
#define S_HN    0                         // 1024 floats
#define S_XN    4096                      // 64 floats (row ||x||^2)
#define S_A     4352                      // 64 x 528 = 33792
#define S_B0    (S_A  + 33792)            // 38144 ; 128 x 272
#define S_B1    (S_B0 + 34816)            // 72960
#define S_V0    (S_B1 + 34816)            // 107776 ; float[4][64]
#define S_V1    (S_V0 + 1024)
#define S_V2    (S_V1 + 1024)
#define S_I0    (S_V2 + 1024)             // int[4][64]
#define S_I1    (S_I0 + 1024)
#define S_IND   (S_I1 + 1024)             // int[64]
#define S_TOTAL (S_IND + 256)             // 113152 B  (2 CTA = 226304 <= 228KB)

// __device__ scratch (allocation-free)
__device__ __align__(16) __nv_bfloat16 g_Eh[KCODES * 128];
__device__ float g_hn[KCODES];
__device__ int   g_pcnt;                  // pair-rescue count
__device__ int4  g_pjobs[NROWS];          // {row, i0, i1, unused}
__device__ int   g_fcnt;                  // full-rescue count
__device__ int   g_frows[NROWS];

// ---------------------------------------------------------------------------
__device__ __forceinline__ unsigned smem_u32(const void* p) {
    unsigned a;
    asm("{ .reg .u64 t; cvta.to.shared.u64 t, %1; cvt.u32.u64 %0, t; }"
        : "=r"(a) : "l"(p));
    return a;
}

#define LDSM_X4(r, addr)                                                      \
    asm volatile("ldmatrix.sync.aligned.m8n8.x4.shared.b16 {%0,%1,%2,%3}, [%4];" \
        : "=r"((r)[0]), "=r"((r)[1]), "=r"((r)[2]), "=r"((r)[3]) : "r"(addr))

#define MMA16816(d, a, b0, b1)                                                \
    asm volatile("mma.sync.aligned.m16n8k16.row.col.f32.bf16.bf16.f32 "       \
        "{%0,%1,%2,%3}, {%4,%5,%6,%7}, {%8,%9}, {%0,%1,%2,%3};"               \
        : "+f"((d)[0]), "+f"((d)[1]), "+f"((d)[2]), "+f"((d)[3])              \
        : "r"((a)[0]), "r"((a)[1]), "r"((a)[2]), "r"((a)[3]), "r"(b0), "r"(b1))

#define CP_COMMIT() asm volatile("cp.async.commit_group;" ::: "memory")
#define CP_WAIT1()  asm volatile("cp.async.wait_group 1;" ::: "memory")

__device__ __forceinline__ unsigned pack_bf16x2(float a, float b) {
    __nv_bfloat162 h = __floats2bfloat162_rn(a, b);
    return *(unsigned*)&h;
}

// top-3 values, top-2 indices; ties -> lower index
struct Top3 { float V0, V1, V2; int I0, I1; };
__device__ __forceinline__ void t3_init(Top3& t) {
    t.V0 = t.V1 = t.V2 = -3.4e38f;
    t.I0 = t.I1 = 0x7fffffff;
}
__device__ __forceinline__ void t3_ins(Top3& t, float v, int i) {
    if (v > t.V0 || (v == t.V0 && i < t.I0)) {
        t.V2 = t.V1; t.V1 = t.V0; t.I1 = t.I0; t.V0 = v; t.I0 = i;
    } else if (v > t.V1 || (v == t.V1 && i < t.I1)) {
        t.V2 = t.V1; t.V1 = v; t.I1 = i;
    } else if (v > t.V2) {
        t.V2 = v;
    }
}

// ---------------------------------------------------------------------------
// prep_e: warp per code. bf16 convert + 0.5||e||^2 + counter reset.
// ---------------------------------------------------------------------------
__global__ void prep_e(const float* __restrict__ embed) {
    int w = (blockIdx.x * blockDim.x + threadIdx.x) >> 5;   // code
    int lane = threadIdx.x & 31;
    if (w == 0 && lane == 0) { g_pcnt = 0; g_fcnt = 0; }
    if (w >= KCODES) return;
    float4 v = ((const float4*)(embed + (size_t)w * 128))[lane];
    float s = v.x * v.x + v.y * v.y + v.z * v.z + v.w * v.w;
#pragma unroll
    for (int off = 16; off > 0; off >>= 1)
        s += __shfl_xor_sync(0xffffffffu, s, off);
    if (lane == 0) g_hn[w] = 0.5f * s;
    uint2 o;
    o.x = pack_bf16x2(v.x, v.y);
    o.y = pack_bf16x2(v.z, v.w);
    ((uint2*)(g_Eh + (size_t)w * 128))[lane] = o;
}

// ---------------------------------------------------------------------------
__device__ __forceinline__ void load_B_async(unsigned sb, int ch, int bufOff, int tid) {
    const char* src = (const char*)(g_Eh + (size_t)ch * 128 * 128);
#pragma unroll
    for (int it = 0; it < 8; it++) {
        int idx = tid + it * 256;
        int r = idx >> 4, kk = idx & 15;
        unsigned dst = sb + bufOff + r * STRIDE_B + kk * 16;
        asm volatile("cp.async.cg.shared.global [%0], [%1], 16;"
                     :: "r"(dst), "l"(src + r * 256 + kk * 16));
    }
}

// ---------------------------------------------------------------------------
// main: 2048 CTAs x 256 threads, 2 CTAs/SM; CTA = 64 rows x 1024 codes.
// Warps 2(row) x 4(code); warp tile 32 x 32.
// ---------------------------------------------------------------------------
__global__ __launch_bounds__(256, 2)
void vq_main(const float* __restrict__ x, const float* __restrict__ embed,
             float* __restrict__ out_ind, float* __restrict__ out_q) {
    extern __shared__ char smem[];
    unsigned sb = smem_u32(smem);
    const int tid  = threadIdx.x;
    const int lane = tid & 31, wid = tid >> 5;
    const int wr = wid & 1, wc = wid >> 1;
    const int rowBase = blockIdx.x * BM;
    float* hnS = (float*)(smem + S_HN);
    float* xnS = (float*)(smem + S_XN);

    // ---- prologue: hn + fused x->bf16-split A tile (+ row norms) ----
    ((float4*)hnS)[tid] = ((const float4*)g_hn)[tid];
    {
        const float4* src = (const float4*)(x + (size_t)rowBase * 128);
#pragma unroll
        for (int it = 0; it < 8; it++) {
            int idx = tid + it * 256;
            int r = idx >> 5, kk = idx & 31;    // one warp covers one row
            float4 v = src[idx];
            float loc = v.x * v.x + v.y * v.y + v.z * v.z + v.w * v.w;
            __nv_bfloat16 h0 = __float2bfloat16(v.x), h1 = __float2bfloat16(v.y);
            __nv_bfloat16 h2 = __float2bfloat16(v.z), h3 = __float2bfloat16(v.w);
            uint2 hi, lo;
            { __nv_bfloat162 t0(h0, h1), t1(h2, h3);
              hi.x = *(unsigned*)&t0; hi.y = *(unsigned*)&t1; }
            lo.x = pack_bf16x2(v.x - __bfloat162float(h0), v.y - __bfloat162float(h1));
            lo.y = pack_bf16x2(v.z - __bfloat162float(h2), v.w - __bfloat162float(h3));
            *(uint2*)(smem + S_A + r * STRIDE_A + kk * 8)       = hi;
            *(uint2*)(smem + S_A + r * STRIDE_A + 256 + kk * 8) = lo;
#pragma unroll
            for (int off = 16; off > 0; off >>= 1)
                loc += __shfl_xor_sync(0xffffffffu, loc, off);
            if (kk == 0) xnS[r] = loc;
        }
    }
    load_B_async(sb, 0, S_B0, tid); CP_COMMIT();
    load_B_async(sb, 1, S_B1, tid); CP_COMMIT();

    Top3 t3[4];
#pragma unroll
    for (int s = 0; s < 4; s++) t3_init(t3[s]);

    const unsigned aRowOff = (unsigned)(wr * 32 + (lane & 15)) * STRIDE_A
                             + ((lane >> 4) * 16);
    const unsigned bRowOff = (unsigned)(wc * 32 + ((lane >> 4) * 8) + (lane & 7)) * STRIDE_B
                             + (((lane >> 3) & 1) * 16);

    for (int ch = 0; ch < 8; ch++) {
        CP_WAIT1();
        __syncthreads();                       // chunk ch resident

        float d[2][4][4];
#pragma unroll
        for (int mt = 0; mt < 2; mt++)
#pragma unroll
            for (int nt = 0; nt < 4; nt++)
#pragma unroll
                for (int e = 0; e < 4; e++) d[mt][nt][e] = 0.f;

        const unsigned Abase = sb + S_A + aRowOff;
        const unsigned Bbase = sb + ((ch & 1) ? S_B1 : S_B0) + bRowOff;

#pragma unroll
        for (int kk = 0; kk < 8; kk++) {
            unsigned ah[2][4], al[2][4];
#pragma unroll
            for (int mt = 0; mt < 2; mt++) {
                LDSM_X4(ah[mt], Abase + mt * (16 * STRIDE_A) + kk * 32);
                LDSM_X4(al[mt], Abase + mt * (16 * STRIDE_A) + 256 + kk * 32);
            }
            unsigned bh[2][4];
#pragma unroll
            for (int j = 0; j < 2; j++)
                LDSM_X4(bh[j], Bbase + j * (16 * STRIDE_B) + kk * 32);
#pragma unroll
            for (int mt = 0; mt < 2; mt++)
#pragma unroll
                for (int nt = 0; nt < 4; nt++) {
                    unsigned b0 = bh[nt >> 1][(nt & 1) * 2];
                    unsigned b1 = bh[nt >> 1][(nt & 1) * 2 + 1];
                    MMA16816(d[mt][nt], ah[mt], b0, b1);   // xh·eh
                    MMA16816(d[mt][nt], al[mt], b0, b1);   // xl·eh
                }
        }

        // ---- fold -0.5||e||^2, update per-row-slot top-3 ----
        const int cb = ch * 128 + wc * 32 + (lane & 3) * 2;
#pragma unroll
        for (int mt = 0; mt < 2; mt++)
#pragma unroll
            for (int h = 0; h < 2; h++) {
                const int s = mt * 2 + h;
#pragma unroll
                for (int nt = 0; nt < 4; nt++)
#pragma unroll
                    for (int e = 0; e < 2; e++) {
                        int code = cb + nt * 8 + e;
                        float v = d[mt][nt][h * 2 + e] - hnS[code];
                        t3_ins(t3[s], v, code);
                    }
            }

        __syncthreads();
        if (ch + 2 < 8) { load_B_async(sb, ch + 2, (ch & 1) ? S_B1 : S_B0, tid); CP_COMMIT(); }
    }

    // ---- merge top-3 across 4 lanes sharing each row (xor 1, 2) ----
#pragma unroll
    for (int s = 0; s < 4; s++) {
#pragma unroll
        for (int off = 1; off <= 2; off <<= 1) {
            float oV0 = __shfl_xor_sync(0xffffffffu, t3[s].V0, off);
            float oV1 = __shfl_xor_sync(0xffffffffu, t3[s].V1, off);
            float oV2 = __shfl_xor_sync(0xffffffffu, t3[s].V2, off);
            int   oI0 = __shfl_xor_sync(0xffffffffu, t3[s].I0, off);
            int   oI1 = __shfl_xor_sync(0xffffffffu, t3[s].I1, off);
            t3_ins(t3[s], oV0, oI0);
            t3_ins(t3[s], oV1, oI1);
            t3_ins(t3[s], oV2, 0x7fffffff);
        }
    }
    if ((lane & 3) == 0) {
#pragma unroll
        for (int s = 0; s < 4; s++) {
            int mt = s >> 1, h = s & 1;
            int r = wr * 32 + mt * 16 + h * 8 + (lane >> 2);
            int o = wc * 64 + r;
            ((float*)(smem + S_V0))[o] = t3[s].V0;
            ((float*)(smem + S_V1))[o] = t3[s].V1;
            ((float*)(smem + S_V2))[o] = t3[s].V2;
            ((int*)(smem + S_I0))[o]   = t3[s].I0;
            ((int*)(smem + S_I1))[o]   = t3[s].I1;
        }
    }
    __syncthreads();

    // ---- merge 4 strips, write ind, classify rescue tiers ----
    if (tid < BM) {
        Top3 t; t3_init(t);
#pragma unroll
        for (int w = 0; w < 4; w++) {
            int o = w * 64 + tid;
            t3_ins(t, ((const float*)(smem + S_V0))[o], ((const int*)(smem + S_I0))[o]);
            t3_ins(t, ((const float*)(smem + S_V1))[o], ((const int*)(smem + S_I1))[o]);
            t3_ins(t, ((const float*)(smem + S_V2))[o], 0x7fffffff);
        }
        int row = rowBase + tid;
        if (out_ind) out_ind[row] = (float)t.I0;
        float T = 0.028f * sqrtf(xnS[tid]);
        if (t.V0 - t.V1 < T) {
            if (t.V0 - t.V2 >= T) {
                int s = atomicAdd(&g_pcnt, 1);
                if (s < NROWS) g_pjobs[s] = make_int4(row, t.I0, t.I1, 0);
            } else {
                int s = atomicAdd(&g_fcnt, 1);
                if (s < NROWS) g_frows[s] = row;
            }
        }
        ((int*)(smem + S_IND))[tid] = t.I0;
    }
    __syncthreads();

    // ---- cooperative gather of quantize rows ----
    if (out_q) {
        const int* inds = (const int*)(smem + S_IND);
        for (int i = tid; i < BM * 32; i += 256) {
            int r = i >> 5, c4 = i & 31;
            float4 v = ((const float4*)(embed + (size_t)inds[r] * 128))[c4];
            ((float4*)(out_q + (size_t)(rowBase + r) * 128))[c4] = v;
        }
    }
}

// ---------------------------------------------------------------------------
// pair rescue: warp per flagged row; exactly re-score 2 candidate codes.
// ---------------------------------------------------------------------------
__global__ __launch_bounds__(256, 8)
void pair_rescue(const float* __restrict__ x,
                 const float* __restrict__ embed,
                 float* __restrict__ out_ind,
                 float* __restrict__ out_q) {
    const int lane = threadIdx.x & 31;
    const int gw = (blockIdx.x * blockDim.x + threadIdx.x) >> 5;
    const int nw = (gridDim.x * blockDim.x) >> 5;
    const int cnt = g_pcnt < NROWS ? g_pcnt : NROWS;

    for (int it = gw; it < cnt; it += nw) {
        int4 job = g_pjobs[it];
        float4 xv = ((const float4*)(x + (size_t)job.x * 128))[lane];
        float s[2];
        int   idx[2] = {job.y, job.z};
#pragma unroll
        for (int c = 0; c < 2; c++) {
            float4 ev = ((const float4*)(embed + (size_t)idx[c] * 128))[lane];
            float p = fmaf(xv.x, ev.x, fmaf(xv.y, ev.y,
                      fmaf(xv.z, ev.z, xv.w * ev.w)));
#pragma unroll
            for (int off = 16; off > 0; off >>= 1)
                p += __shfl_xor_sync(0xffffffffu, p, off);
            s[c] = p - g_hn[idx[c]];
        }
        float B = s[0]; int I = idx[0];
        if (s[1] > B || (s[1] == B && idx[1] < I)) { B = s[1]; I = idx[1]; }
        if (lane == 0 && out_ind) out_ind[job.x] = (float)I;
        if (out_q)
            ((float4*)(out_q + (size_t)job.x * 128))[lane] =
                ((const float4*)(embed + (size_t)I * 128))[lane];
    }
}

// ---------------------------------------------------------------------------
// BATCHED full rescue: 16 rows/block, embed streamed through smem (64-code
// chunks shared by all 16 rows).
// ---------------------------------------------------------------------------
#define R_ROWS 16
__global__ __launch_bounds__(256, 1)
void full_rescue(const float* __restrict__ x,
                 const float* __restrict__ embed,
                 float* __restrict__ out_ind,
                 float* __restrict__ out_q) {
    __shared__ float xs[R_ROWS * 128];
    __shared__ float es[64 * 128];
    __shared__ float hns[64];
    __shared__ int   rowIdx[R_ROWS];
    __shared__ float rbv[R_ROWS][16];
    __shared__ int   rbi[R_ROWS][16];
    const int tid = threadIdx.x;
    const int myRow = tid & 15;
    const int cg    = tid >> 4;
    const int cnt = g_fcnt < NROWS ? g_fcnt : NROWS;

    for (int base = blockIdx.x * R_ROWS; base < cnt; base += gridDim.x * R_ROWS) {
        const int nr = (cnt - base < R_ROWS) ? (cnt - base) : R_ROWS;
        if (tid < R_ROWS)
            rowIdx[tid] = g_frows[base + ((tid < nr) ? tid : 0)];
        __syncthreads();
        for (int i = tid; i < nr * 32; i += 256) {
            int r = i >> 5, c4 = i & 31;
            ((float4*)xs)[r * 32 + c4] =
                ((const float4*)(x + (size_t)rowIdx[r] * 128))[c4];
        }

        float bv = -3.4e38f;
        int   bi = 0;
        for (int ch = 0; ch < 16; ch++) {
            __syncthreads();
            for (int i = tid; i < 64 * 32; i += 256)
                ((float4*)es)[i] = ((const float4*)(embed + (size_t)ch * 64 * 128))[i];
            if (tid < 64) hns[tid] = g_hn[ch * 64 + tid];
            __syncthreads();
            if (myRow < nr) {
                const float4* x4 = (const float4*)(xs + myRow * 128);
#pragma unroll
                for (int j = 0; j < 4; j++) {
                    int lc = cg * 4 + j;
                    const float4* e4 = (const float4*)(es + lc * 128);
                    float s0 = 0.f, s1 = 0.f, s2 = 0.f, s3 = 0.f;
#pragma unroll
                    for (int i = 0; i < 8; i++) {
                        float4 xa = x4[i * 4 + 0], ea = e4[i * 4 + 0];
                        float4 xb = x4[i * 4 + 1], eb = e4[i * 4 + 1];
                        float4 xc = x4[i * 4 + 2], ec = e4[i * 4 + 2];
                        float4 xd = x4[i * 4 + 3], ed = e4[i * 4 + 3];
                        s0 = fmaf(xa.x, ea.x, fmaf(xa.y, ea.y, fmaf(xa.z, ea.z, fmaf(xa.w, ea.w, s0))));
                        s1 = fmaf(xb.x, eb.x, fmaf(xb.y, eb.y, fmaf(xb.z, eb.z, fmaf(xb.w, eb.w, s1))));
                        s2 = fmaf(xc.x, ec.x, fmaf(xc.y, ec.y, fmaf(xc.z, ec.z, fmaf(xc.w, ec.w, s2))));
                        s3 = fmaf(xd.x, ed.x, fmaf(xd.y, ed.y, fmaf(xd.z, ed.z, fmaf(xd.w, ed.w, s3))));
                    }
                    float s = (s0 + s1) + (s2 + s3) - hns[lc];
                    int code = ch * 64 + lc;
                    if (s > bv) { bv = s; bi = code; }
                }
            }
        }
        rbv[myRow][cg] = bv;
        rbi[myRow][cg] = bi;
        __syncthreads();

        if (tid < nr) {
            float B = rbv[tid][0]; int I = rbi[tid][0];
#pragma unroll
            for (int g = 1; g < 16; g++) {
                float ov = rbv[tid][g]; int oi = rbi[tid][g];
                if (ov > B || (ov == B && oi < I)) { B = ov; I = oi; }
            }
            if (out_ind) out_ind[rowIdx[tid]] = (float)I;
            rbi[tid][0] = I;
        }
        __syncthreads();
        if (out_q) {
            for (int i = tid; i < nr * 32; i += 256) {
                int r = i >> 5, c4 = i & 31;
                ((float4*)(out_q + (size_t)rowIdx[r] * 128))[c4] =
                    ((const float4*)(embed + (size_t)rbi[r][0] * 128))[c4];
            }
        }
        __syncthreads();
    }
}

// ---------------------------------------------------------------------------
extern "C" void kernel_launch(void* const* d_in, const int* in_sizes, int n_in,
                              void* d_out, int out_size) {
    const float* x     = (const float*)d_in[0];
    const float* embed = (const float*)d_in[1];
    const int N = in_sizes[0] / 128;   // 131072

    float* out     = (float*)d_out;
    float* out_ind = out;              // layout: [ind (N)][quantize (N*128)]
    float* out_q   = out + N;
    long long os = (long long)out_size;
    if (os == (long long)N * 128) { out_ind = nullptr; out_q = out; }
    else if (os == (long long)N)  { out_q = nullptr; }

    prep_e<<<KCODES / 8, 256>>>(embed);

    cudaFuncSetAttribute(vq_main, cudaFuncAttributeMaxDynamicSharedMemorySize,
                         S_TOTAL);
    vq_main<<<N / BM, 256, S_TOTAL>>>(x, embed, out_ind, out_q);

    pair_rescue<<<512, 256>>>(x, embed, out_ind, out_q);
    full_rescue<<<512, 256>>>(x, embed, out_ind, out_q);
}